// round 3
// baseline (speedup 1.0000x reference)
#include <cuda_runtime.h>
#include <cuda_bf16.h>
#include <cstddef>
#include <math.h>

// Problem dims
static constexpr int B_  = 32;
static constexpr int T_  = 1024;
static constexpr int H_  = 512;
static constexpr int G4  = 2048;   // 4*H gate columns per layer
static constexpr int NCTA = 128;   // persistent CTAs, each owns 4 hidden cols

// SMEM strides (bank-conflict padding)
static constexpr int AS_STRIDE = 68;   // precompute tiles: 68%32=4, 68*4B %16B == 0
static constexpr int W_STRIDE  = 520;  // weight rows: 520%32=8 -> jj groups hit distinct banks

// Recurrent SMEM layout (floats): weights | h staging | z partials
static constexpr int W_S_FLOATS = 3 * 16 * W_STRIDE;      // 24960
static constexpr int H_S_FLOATS = H_ * B_;                // 16384
static constexpr int Z_S_FLOATS = 2 * 16 * B_;            // 1024
static constexpr int SMEM_BYTES = (W_S_FLOATS + H_S_FLOATS + Z_S_FLOATS) * 4; // 169472

// -------- device-global scratch (allocations forbidden) --------
__device__ float    g_Z0p[(size_t)T_ * G4 * B_];   // [t][gate_col][b], 268 MB (bss)
__device__ float    g_h[2][2][H_][B_];             // [layer][parity][col][b]
__device__ unsigned g_count;                       // grid-barrier counter

__device__ __forceinline__ float fsigm(float z) { return 1.0f / (1.0f + __expf(-z)); }

// -------- init: reset barrier counter + zero states (every launch, graph-safe) --------
__global__ void init_kernel() {
    int idx = blockIdx.x * blockDim.x + threadIdx.x;
    if (idx == 0) g_count = 0u;
    if (idx < 2 * 2 * H_ * B_) reinterpret_cast<float*>(g_h)[idx] = 0.0f;
}

// -------- precompute: Z0p[t][j][b] = (x @ Wi0^T)[m=b*T+t][j] + bi0[j] + bs0[j] --------
// M=32768, N=2048, K=512. 64x64 tile, 256 threads, 4x4 register tile per thread.
__global__ void __launch_bounds__(256) precompute_kernel(
    const float* __restrict__ x, const float* __restrict__ Wi,
    const float* __restrict__ bi, const float* __restrict__ bs)
{
    __shared__ float As[16 * AS_STRIDE];   // transposed [k][64]
    __shared__ float Bs[16 * AS_STRIDE];
    const int tid = threadIdx.x;
    const int m0 = blockIdx.y * 64;
    const int j0 = blockIdx.x * 64;
    const int lr = tid >> 2;     // row within tile (0..63)
    const int lq = tid & 3;      // k-quad (4 floats)
    const int tx = tid & 15;
    const int ty = tid >> 4;

    float C[4][4] = {};
    const float* Arow = x  + (size_t)(m0 + lr) * H_ + lq * 4;
    const float* Brow = Wi + (size_t)(j0 + lr) * H_ + lq * 4;

    for (int kc = 0; kc < H_; kc += 16) {
        float4 a4 = *(const float4*)(Arow + kc);
        float4 b4 = *(const float4*)(Brow + kc);
        __syncthreads();
        As[(lq * 4 + 0) * AS_STRIDE + lr] = a4.x;
        As[(lq * 4 + 1) * AS_STRIDE + lr] = a4.y;
        As[(lq * 4 + 2) * AS_STRIDE + lr] = a4.z;
        As[(lq * 4 + 3) * AS_STRIDE + lr] = a4.w;
        Bs[(lq * 4 + 0) * AS_STRIDE + lr] = b4.x;
        Bs[(lq * 4 + 1) * AS_STRIDE + lr] = b4.y;
        Bs[(lq * 4 + 2) * AS_STRIDE + lr] = b4.z;
        Bs[(lq * 4 + 3) * AS_STRIDE + lr] = b4.w;
        __syncthreads();
        #pragma unroll
        for (int k = 0; k < 16; k++) {
            float4 av = *(const float4*)&As[k * AS_STRIDE + ty * 4];
            float4 bv = *(const float4*)&Bs[k * AS_STRIDE + tx * 4];
            C[0][0] = fmaf(av.x, bv.x, C[0][0]); C[0][1] = fmaf(av.x, bv.y, C[0][1]);
            C[0][2] = fmaf(av.x, bv.z, C[0][2]); C[0][3] = fmaf(av.x, bv.w, C[0][3]);
            C[1][0] = fmaf(av.y, bv.x, C[1][0]); C[1][1] = fmaf(av.y, bv.y, C[1][1]);
            C[1][2] = fmaf(av.y, bv.z, C[1][2]); C[1][3] = fmaf(av.y, bv.w, C[1][3]);
            C[2][0] = fmaf(av.z, bv.x, C[2][0]); C[2][1] = fmaf(av.z, bv.y, C[2][1]);
            C[2][2] = fmaf(av.z, bv.z, C[2][2]); C[2][3] = fmaf(av.z, bv.w, C[2][3]);
            C[3][0] = fmaf(av.w, bv.x, C[3][0]); C[3][1] = fmaf(av.w, bv.y, C[3][1]);
            C[3][2] = fmaf(av.w, bv.z, C[3][2]); C[3][3] = fmaf(av.w, bv.w, C[3][3]);
        }
    }
    #pragma unroll
    for (int i = 0; i < 4; i++) {
        int m = m0 + ty * 4 + i;
        int bb = m >> 10, tt = m & 1023;
        #pragma unroll
        for (int jc = 0; jc < 4; jc++) {
            int jg = j0 + tx * 4 + jc;
            float v = C[i][jc] + bi[jg] + bs[jg];
            g_Z0p[((size_t)tt * G4 + jg) * B_ + bb] = v;
        }
    }
}

// -------- recurrent persistent kernel --------
__global__ void __launch_bounds__(256, 1) recurrent_kernel(
    const float* __restrict__ x, const float* __restrict__ Wi,
    const float* __restrict__ bi, const float* __restrict__ Ws,
    const float* __restrict__ bs, float* __restrict__ out)
{
    extern __shared__ float smem[];
    float* w_s = smem;                       // [3][16][W_STRIDE]
    float* h_s = smem + W_S_FLOATS;          // [512][32]
    float* z_s = h_s + H_S_FLOATS;           // [2][16][32]

    const int tid = threadIdx.x;
    const int cta = blockIdx.x;

    // ---- load weight slices into SMEM (once) ----
    // slice 0: Ws layer0, slice 1: Wi layer1, slice 2: Ws layer1
    for (int idx = tid; idx < 48 * 128; idx += 256) {
        int r = idx >> 7, q = idx & 127;
        int s = r >> 4, jjr = r & 15;
        int g = jjr >> 2, cc = jjr & 3;
        int grow = g * H_ + cta * 4 + cc;
        const float* src;
        if (s == 0)      src = Ws + (size_t)grow * H_;
        else if (s == 1) src = Wi + (size_t)(G4 + grow) * H_;
        else             src = Ws + (size_t)(G4 + grow) * H_;
        *(float4*)(w_s + r * W_STRIDE + q * 4) = *(const float4*)(src + q * 4);
    }

    // ---- GEMM thread constants: 8 b-groups x 16 gate-cols x 2 K-splits ----
    const int b4 = tid & 7;           // b base = b4*4
    const int jj = (tid >> 3) & 15;   // gate-col within slice: jj = g*4 + cc
    const int ks = tid >> 7;          // K-split half
    const int gg_ = jj >> 2, ccg = jj & 3;
    const int jcol = gg_ * H_ + cta * 4 + ccg;
    const float b1v = (ks == 0) ? (bi[G4 + jcol] + bs[G4 + jcol]) : 0.0f;

    // ---- cell-update thread constants (tid < 128) ----
    const int ub = tid & 31;          // batch
    const int ucc = tid >> 5;         // local hidden col 0..3
    const int col = cta * 4 + ucc;

    float c0 = 0.0f, c1 = 0.0f, h0v = 0.0f;
    unsigned epoch = 0;

    const float4* hv = (const float4*)h_s;     // [512][8] float4 view
    const float4* hp = hv + ks * 256 * 8 + b4; // this thread's K-half, b-group

    #define GEMM_SLICE(SLICE, ACC)                                              \
    {                                                                           \
        const float* wrow = w_s + ((SLICE) * 16 + jj) * W_STRIDE + ks * 256;    \
        _Pragma("unroll 4")                                                     \
        for (int k0 = 0; k0 < 256; k0 += 4) {                                   \
            float4 w4 = *(const float4*)(wrow + k0);                            \
            float4 ha = hp[(k0 + 0) * 8];                                       \
            float4 hb = hp[(k0 + 1) * 8];                                       \
            float4 hc = hp[(k0 + 2) * 8];                                       \
            float4 hd = hp[(k0 + 3) * 8];                                       \
            ACC.x = fmaf(ha.x, w4.x, ACC.x); ACC.y = fmaf(ha.y, w4.x, ACC.y);   \
            ACC.z = fmaf(ha.z, w4.x, ACC.z); ACC.w = fmaf(ha.w, w4.x, ACC.w);   \
            ACC.x = fmaf(hb.x, w4.y, ACC.x); ACC.y = fmaf(hb.y, w4.y, ACC.y);   \
            ACC.z = fmaf(hb.z, w4.y, ACC.z); ACC.w = fmaf(hb.w, w4.y, ACC.w);   \
            ACC.x = fmaf(hc.x, w4.z, ACC.x); ACC.y = fmaf(hc.y, w4.z, ACC.y);   \
            ACC.z = fmaf(hc.z, w4.z, ACC.z); ACC.w = fmaf(hc.w, w4.z, ACC.w);   \
            ACC.x = fmaf(hd.x, w4.w, ACC.x); ACC.y = fmaf(hd.y, w4.w, ACC.y);   \
            ACC.z = fmaf(hd.z, w4.w, ACC.z); ACC.w = fmaf(hd.w, w4.w, ACC.w);   \
        }                                                                       \
    }

    #define STAGE_H(SRC)                                                        \
    {                                                                           \
        const float4* s4 = (const float4*)(SRC);                                \
        float4* d4 = (float4*)h_s;                                              \
        _Pragma("unroll")                                                       \
        for (int i = 0; i < 16; i++) d4[tid + i * 256] = s4[tid + i * 256];     \
    }

    #define GRID_SYNC()                                                         \
    {                                                                           \
        __syncthreads();                                                        \
        if (tid == 0) {                                                         \
            __threadfence();                                                    \
            atomicAdd(&g_count, 1u);                                            \
            ++epoch;                                                            \
            unsigned target = epoch * NCTA;                                     \
            while (*(volatile unsigned*)&g_count < target) { }                  \
            __threadfence();                                                    \
        }                                                                       \
        __syncthreads();                                                        \
    }

    #define CELL_GATES(ZI, ZF, ZG, ZO)                                          \
        float zi = z_s[((0 * 4 + ucc)) * 32 + ub] + z_s[(16 + 0 * 4 + ucc) * 32 + ub]; \
        float zf = z_s[((1 * 4 + ucc)) * 32 + ub] + z_s[(16 + 1 * 4 + ucc) * 32 + ub]; \
        float zg = z_s[((2 * 4 + ucc)) * 32 + ub] + z_s[(16 + 2 * 4 + ucc) * 32 + ub]; \
        float zo = z_s[((3 * 4 + ucc)) * 32 + ub] + z_s[(16 + 3 * 4 + ucc) * 32 + ub]; \
        float ZI = fsigm(zi); float ZF = fsigm(zf);                             \
        float ZG = tanhf(zg); float ZO = fsigm(zo);

    for (int t = 0; t < T_; t++) {
        const int cur = t & 1, prv = cur ^ 1;

        // ================= Phase A: layer 0 =================
        __syncthreads();                      // h_s/z_s consumers from prior phase done
        STAGE_H(&g_h[0][prv][0][0]);
        float4 acc;
        if (ks == 0) acc = *(const float4*)&g_Z0p[((size_t)t * G4 + jcol) * B_ + b4 * 4];
        else         acc = make_float4(0.f, 0.f, 0.f, 0.f);
        __syncthreads();                      // h_s ready
        GEMM_SLICE(0, acc);
        *(float4*)&z_s[(ks * 16 + jj) * 32 + b4 * 4] = acc;
        __syncthreads();
        if (tid < 128) {
            CELL_GATES(ig, fg, gv, og);
            c0 = fmaf(fg, c0, ig * gv);
            float xv = x[((size_t)ub * T_ + t) * H_ + col];
            h0v = fmaf(og, tanhf(c0), xv);    // residual: + x_t
            g_h[0][cur][col][ub] = h0v;
        }
        GRID_SYNC();

        // ================= Phase B: layer 1 =================
        STAGE_H(&g_h[0][cur][0][0]);
        float4 acc1 = make_float4(b1v, b1v, b1v, b1v);
        __syncthreads();
        GEMM_SLICE(1, acc1);                  // h0_cur @ Wi1^T
        __syncthreads();                      // everyone done with h_s
        STAGE_H(&g_h[1][prv][0][0]);
        __syncthreads();
        GEMM_SLICE(2, acc1);                  // + h1_prev @ Ws1^T
        *(float4*)&z_s[(ks * 16 + jj) * 32 + b4 * 4] = acc1;
        __syncthreads();
        if (tid < 128) {
            CELL_GATES(ig, fg, gv, og);
            c1 = fmaf(fg, c1, ig * gv);
            float h1v = fmaf(og, tanhf(c1), h0v);  // residual: + h0
            g_h[1][cur][col][ub] = h1v;
            out[((size_t)ub * T_ + t) * H_ + col] = h1v;
            if (t == T_ - 1) {
                float* hf = out + (size_t)B_ * T_ * H_;     // h_f: (B, L, H)
                float* cf = hf + (size_t)B_ * 2 * H_;       // c_f: (B, L, H)
                hf[((size_t)ub * 2 + 0) * H_ + col] = h0v;
                hf[((size_t)ub * 2 + 1) * H_ + col] = h1v;
                cf[((size_t)ub * 2 + 0) * H_ + col] = c0;
                cf[((size_t)ub * 2 + 1) * H_ + col] = c1;
            }
        }
        GRID_SYNC();
    }

    #undef GEMM_SLICE
    #undef STAGE_H
    #undef GRID_SYNC
    #undef CELL_GATES
}

extern "C" void kernel_launch(void* const* d_in, const int* in_sizes, int n_in,
                              void* d_out, int out_size)
{
    const float* x  = (const float*)d_in[0];
    const float* Wi = (const float*)d_in[1];
    const float* bi = (const float*)d_in[2];
    const float* Ws = (const float*)d_in[3];
    const float* bs = (const float*)d_in[4];
    float* out = (float*)d_out;

    cudaFuncSetAttribute(recurrent_kernel,
                         cudaFuncAttributeMaxDynamicSharedMemorySize, SMEM_BYTES);

    init_kernel<<<256, 256>>>();
    precompute_kernel<<<dim3(32, 512), 256>>>(x, Wi, bi, bs);
    recurrent_kernel<<<NCTA, 256, SMEM_BYTES>>>(x, Wi, bi, Ws, bs, out);
}

// round 4
// speedup vs baseline: 1.1780x; 1.1780x over previous
#include <cuda_runtime.h>
#include <cuda_bf16.h>
#include <cstddef>
#include <math.h>

// Problem dims
static constexpr int B_  = 32;
static constexpr int T_  = 1024;
static constexpr int H_  = 512;
static constexpr int G4  = 2048;   // 4*H gate columns per layer
static constexpr int NCTA = 128;   // persistent CTAs, each owns 4 hidden cols
static constexpr int THR  = 512;   // threads per recurrent CTA

// SMEM strides (bank-conflict padding)
static constexpr int AS_STRIDE = 68;   // precompute tiles
static constexpr int W_STRIDE  = 516;  // 516%32=4 -> 8 jj rows hit distinct banks; 516*4B%16==0
static constexpr int Z_STRIDE  = 36;   // 36%32=4  -> conflict-free z stores; 16B aligned rows

// Recurrent SMEM layout (floats): weights | h staging | z partials
static constexpr int W_S_FLOATS = 3 * 16 * W_STRIDE;        // 24768
static constexpr int H_S_FLOATS = H_ * B_;                  // 16384
static constexpr int Z_S_FLOATS = 2 * 8 * 16 * Z_STRIDE;    // 9216
static constexpr int SMEM_BYTES = (W_S_FLOATS + H_S_FLOATS + Z_S_FLOATS) * 4; // 201472

// -------- device-global scratch (allocations forbidden) --------
__device__ float    g_Z0p[(size_t)T_ * G4 * B_];   // [t][gate_col][b]
__device__ float    g_h[2][2][H_][B_];             // [layer][parity][col][b]
__device__ unsigned g_count;                       // grid-barrier arrivals (cumulative)
__device__ volatile unsigned g_release;            // grid-barrier release epoch

__device__ __forceinline__ float fsigm(float z) { return 1.0f / (1.0f + __expf(-z)); }
__device__ __forceinline__ float ftanh(float z) { return 2.0f / (1.0f + __expf(-2.0f * z)) - 1.0f; }

// -------- init: reset barrier + zero states (every launch, graph-safe) --------
__global__ void init_kernel() {
    int idx = blockIdx.x * blockDim.x + threadIdx.x;
    if (idx == 0) { g_count = 0u; g_release = 0u; }
    if (idx < 2 * 2 * H_ * B_) reinterpret_cast<float*>(g_h)[idx] = 0.0f;
}

// -------- precompute: Z0p[t][j][b] = (x @ Wi0^T)[m=b*T+t][j] + bi0[j] + bs0[j] --------
__global__ void __launch_bounds__(256) precompute_kernel(
    const float* __restrict__ x, const float* __restrict__ Wi,
    const float* __restrict__ bi, const float* __restrict__ bs)
{
    __shared__ float As[16 * AS_STRIDE];
    __shared__ float Bs[16 * AS_STRIDE];
    const int tid = threadIdx.x;
    const int m0 = blockIdx.y * 64;
    const int j0 = blockIdx.x * 64;
    const int lr = tid >> 2;
    const int lq = tid & 3;
    const int tx = tid & 15;
    const int ty = tid >> 4;

    float C[4][4] = {};
    const float* Arow = x  + (size_t)(m0 + lr) * H_ + lq * 4;
    const float* Brow = Wi + (size_t)(j0 + lr) * H_ + lq * 4;

    for (int kc = 0; kc < H_; kc += 16) {
        float4 a4 = *(const float4*)(Arow + kc);
        float4 b4 = *(const float4*)(Brow + kc);
        __syncthreads();
        As[(lq * 4 + 0) * AS_STRIDE + lr] = a4.x;
        As[(lq * 4 + 1) * AS_STRIDE + lr] = a4.y;
        As[(lq * 4 + 2) * AS_STRIDE + lr] = a4.z;
        As[(lq * 4 + 3) * AS_STRIDE + lr] = a4.w;
        Bs[(lq * 4 + 0) * AS_STRIDE + lr] = b4.x;
        Bs[(lq * 4 + 1) * AS_STRIDE + lr] = b4.y;
        Bs[(lq * 4 + 2) * AS_STRIDE + lr] = b4.z;
        Bs[(lq * 4 + 3) * AS_STRIDE + lr] = b4.w;
        __syncthreads();
        #pragma unroll
        for (int k = 0; k < 16; k++) {
            float4 av = *(const float4*)&As[k * AS_STRIDE + ty * 4];
            float4 bv = *(const float4*)&Bs[k * AS_STRIDE + tx * 4];
            C[0][0] = fmaf(av.x, bv.x, C[0][0]); C[0][1] = fmaf(av.x, bv.y, C[0][1]);
            C[0][2] = fmaf(av.x, bv.z, C[0][2]); C[0][3] = fmaf(av.x, bv.w, C[0][3]);
            C[1][0] = fmaf(av.y, bv.x, C[1][0]); C[1][1] = fmaf(av.y, bv.y, C[1][1]);
            C[1][2] = fmaf(av.y, bv.z, C[1][2]); C[1][3] = fmaf(av.y, bv.w, C[1][3]);
            C[2][0] = fmaf(av.z, bv.x, C[2][0]); C[2][1] = fmaf(av.z, bv.y, C[2][1]);
            C[2][2] = fmaf(av.z, bv.z, C[2][2]); C[2][3] = fmaf(av.z, bv.w, C[2][3]);
            C[3][0] = fmaf(av.w, bv.x, C[3][0]); C[3][1] = fmaf(av.w, bv.y, C[3][1]);
            C[3][2] = fmaf(av.w, bv.z, C[3][2]); C[3][3] = fmaf(av.w, bv.w, C[3][3]);
        }
    }
    #pragma unroll
    for (int i = 0; i < 4; i++) {
        int m = m0 + ty * 4 + i;
        int bb = m >> 10, tt = m & 1023;
        #pragma unroll
        for (int jc = 0; jc < 4; jc++) {
            int jg = j0 + tx * 4 + jc;
            float v = C[i][jc] + bi[jg] + bs[jg];
            g_Z0p[((size_t)tt * G4 + jg) * B_ + bb] = v;
        }
    }
}

// -------- recurrent persistent kernel (layer-pipelined, one grid sync/step) ----
// Iteration t (0..T_): layer0 computes time t (t<T_); layer1 computes time t-1 (t>=1).
__global__ void __launch_bounds__(THR, 1) recurrent_kernel(
    const float* __restrict__ x, const float* __restrict__ Wi,
    const float* __restrict__ bi, const float* __restrict__ Ws,
    const float* __restrict__ bs, float* __restrict__ out)
{
    extern __shared__ float smem[];
    float* w_s = smem;                       // [3][16][W_STRIDE]
    float* h_s = smem + W_S_FLOATS;          // [512][32]
    float* z_s = h_s + H_S_FLOATS;           // [2][8][16][Z_STRIDE]

    const int tid = threadIdx.x;
    const int cta = blockIdx.x;

    // ---- load weight slices into SMEM once ----
    // slice 0: Ws layer0, slice 1: Wi layer1, slice 2: Ws layer1
    for (int idx = tid; idx < 48 * 128; idx += THR) {
        int r = idx >> 7, q = idx & 127;
        int s = r >> 4, jjr = r & 15;
        int g = jjr >> 2, cc = jjr & 3;
        int grow = g * H_ + cta * 4 + cc;
        const float* src;
        if (s == 0)      src = Ws + (size_t)grow * H_;
        else if (s == 1) src = Wi + (size_t)(G4 + grow) * H_;
        else             src = Ws + (size_t)(G4 + grow) * H_;
        *(float4*)(w_s + r * W_STRIDE + q * 4) = *(const float4*)(src + q * 4);
    }

    // ---- GEMM thread constants: bg(4 b-groups of 8) x jj(16 cols) x ks(8 K-splits) ----
    const int bg = tid & 3;
    const int jj = (tid >> 2) & 15;
    const int ks = tid >> 6;

    // ---- cell thread constants (tid < 256): layer, 4 cols, 32 b ----
    const bool is_cell = tid < 256;
    const int layer = (tid >> 7) & 1;
    const int ub  = tid & 31;
    const int ucc = (tid >> 5) & 3;
    const int col = cta * 4 + ucc;

    float b1g0 = 0.f, b1g1 = 0.f, b1g2 = 0.f, b1g3 = 0.f;
    if (is_cell && layer == 1) {
        b1g0 = bi[G4 + 0 * H_ + col] + bs[G4 + 0 * H_ + col];
        b1g1 = bi[G4 + 1 * H_ + col] + bs[G4 + 1 * H_ + col];
        b1g2 = bi[G4 + 2 * H_ + col] + bs[G4 + 2 * H_ + col];
        b1g3 = bi[G4 + 3 * H_ + col] + bs[G4 + 3 * H_ + col];
    }

    float cst = 0.0f;     // this cell thread's c (layer 0 or 1)
    unsigned epoch = 0;

    const ulonglong2* h2 = (const ulonglong2*)h_s;   // packed f32-pair view, 16B units

    // packed-pair GEMM: acc (A01..A67) covers b = bg*8..bg*8+8 for gate col jj
    #define GEMM_SLICE(SLICE)                                                        \
    {                                                                                \
        const float* wrow = w_s + ((SLICE) * 16 + jj) * W_STRIDE + ks * 64;          \
        _Pragma("unroll 4")                                                          \
        for (int k0 = 0; k0 < 64; k0 += 4) {                                         \
            float4 w4 = *(const float4*)(wrow + k0);                                 \
            _Pragma("unroll")                                                        \
            for (int i = 0; i < 4; i++) {                                            \
                float wv = (i == 0) ? w4.x : (i == 1) ? w4.y : (i == 2) ? w4.z : w4.w; \
                unsigned long long w2;                                               \
                asm("mov.b64 %0, {%1, %1};" : "=l"(w2) : "f"(wv));                   \
                int kk = ks * 64 + k0 + i;                                           \
                ulonglong2 hA = h2[kk * 8 + bg * 2 + 0];                             \
                ulonglong2 hB = h2[kk * 8 + bg * 2 + 1];                             \
                asm("fma.rn.f32x2 %0, %1, %2, %0;" : "+l"(A01) : "l"(hA.x), "l"(w2)); \
                asm("fma.rn.f32x2 %0, %1, %2, %0;" : "+l"(A23) : "l"(hA.y), "l"(w2)); \
                asm("fma.rn.f32x2 %0, %1, %2, %0;" : "+l"(A45) : "l"(hB.x), "l"(w2)); \
                asm("fma.rn.f32x2 %0, %1, %2, %0;" : "+l"(A67) : "l"(hB.y), "l"(w2)); \
            }                                                                        \
        }                                                                            \
    }

    #define STORE_Z(LAYER)                                                           \
    {                                                                                \
        ulonglong2* zp = (ulonglong2*)(z_s + (((LAYER) * 8 + ks) * 16 + jj) * Z_STRIDE + bg * 8); \
        zp[0] = make_ulonglong2(A01, A23);                                           \
        zp[1] = make_ulonglong2(A45, A67);                                           \
    }

    for (int t = 0; t <= T_; t++) {
        const int cur = t & 1, prv = cur ^ 1;

        // ---- prefetches (all independent of this iteration's compute) ----
        float4 h0p[8], h1p[8];
        {
            const float4* s0 = (const float4*)&g_h[0][prv][0][0];  // h0(t-1)
            const float4* s1 = (const float4*)&g_h[1][cur][0][0];  // h1(t-2)
            #pragma unroll
            for (int i = 0; i < 8; i++) h0p[i] = s0[tid + i * THR];
            #pragma unroll
            for (int i = 0; i < 8; i++) h1p[i] = s1[tid + i * THR];
        }
        float zp0 = 0.f, zp1 = 0.f, zp2 = 0.f, zp3 = 0.f, xv = 0.f;
        if (is_cell && layer == 0 && t < T_) {
            zp0 = g_Z0p[((size_t)t * G4 + 0 * H_ + col) * B_ + ub];
            zp1 = g_Z0p[((size_t)t * G4 + 1 * H_ + col) * B_ + ub];
            zp2 = g_Z0p[((size_t)t * G4 + 2 * H_ + col) * B_ + ub];
            zp3 = g_Z0p[((size_t)t * G4 + 3 * H_ + col) * B_ + ub];
            xv  = x[((size_t)ub * T_ + t) * H_ + col];
        }

        // ---- stage h0(t-1) ----
        {
            float4* d4 = (float4*)h_s;
            #pragma unroll
            for (int i = 0; i < 8; i++) d4[tid + i * THR] = h0p[i];
        }
        __syncthreads();                       // (a) h_s = h0(t-1)

        // ---- slice 0: layer0 recurrent GEMM ----
        {
            unsigned long long A01 = 0, A23 = 0, A45 = 0, A67 = 0;
            GEMM_SLICE(0);
            STORE_Z(0);
        }

        // ---- slice 1: layer1 input GEMM (same h_s) ----
        unsigned long long A01 = 0, A23 = 0, A45 = 0, A67 = 0;
        GEMM_SLICE(1);

        float h0res = 0.f;
        if (is_cell && layer == 1) h0res = h_s[col * 32 + ub];  // h0(t-1), residual for layer1

        __syncthreads();                       // (b) all h_s reads done
        {
            float4* d4 = (float4*)h_s;
            #pragma unroll
            for (int i = 0; i < 8; i++) d4[tid + i * THR] = h1p[i];
        }
        __syncthreads();                       // (c) h_s = h1(t-2)

        // ---- slice 2: layer1 recurrent GEMM (accumulates into A) ----
        GEMM_SLICE(2);
        STORE_Z(1);
        __syncthreads();                       // (d) z ready

        // ---- cell updates ----
        if (is_cell) {
            if (layer == 0) {
                if (t < T_) {
                    float zi = zp0, zf = zp1, zg = zp2, zo = zp3;
                    #pragma unroll
                    for (int p = 0; p < 8; p++) {
                        const float* zr = z_s + (0 * 8 + p) * 16 * Z_STRIDE;
                        zi += zr[(0 * 4 + ucc) * Z_STRIDE + ub];
                        zf += zr[(1 * 4 + ucc) * Z_STRIDE + ub];
                        zg += zr[(2 * 4 + ucc) * Z_STRIDE + ub];
                        zo += zr[(3 * 4 + ucc) * Z_STRIDE + ub];
                    }
                    cst = fmaf(fsigm(zf), cst, fsigm(zi) * ftanh(zg));
                    float hv = fmaf(fsigm(zo), ftanh(cst), xv);
                    g_h[0][cur][col][ub] = hv;
                    if (t == T_ - 1) {
                        float* hf = out + (size_t)B_ * T_ * H_;
                        float* cf = hf + (size_t)B_ * 2 * H_;
                        hf[((size_t)ub * 2 + 0) * H_ + col] = hv;
                        cf[((size_t)ub * 2 + 0) * H_ + col] = cst;
                    }
                }
            } else {
                if (t >= 1) {
                    float zi = b1g0, zf = b1g1, zg = b1g2, zo = b1g3;
                    #pragma unroll
                    for (int p = 0; p < 8; p++) {
                        const float* zr = z_s + (1 * 8 + p) * 16 * Z_STRIDE;
                        zi += zr[(0 * 4 + ucc) * Z_STRIDE + ub];
                        zf += zr[(1 * 4 + ucc) * Z_STRIDE + ub];
                        zg += zr[(2 * 4 + ucc) * Z_STRIDE + ub];
                        zo += zr[(3 * 4 + ucc) * Z_STRIDE + ub];
                    }
                    cst = fmaf(fsigm(zf), cst, fsigm(zi) * ftanh(zg));
                    float hv = fmaf(fsigm(zo), ftanh(cst), h0res);
                    g_h[1][prv][col][ub] = hv;                          // h1(t-1)
                    out[((size_t)ub * T_ + (t - 1)) * H_ + col] = hv;
                    if (t == T_) {
                        float* hf = out + (size_t)B_ * T_ * H_;
                        float* cf = hf + (size_t)B_ * 2 * H_;
                        hf[((size_t)ub * 2 + 1) * H_ + col] = hv;
                        cf[((size_t)ub * 2 + 1) * H_ + col] = cst;
                    }
                }
            }
        }

        // ---- grid barrier (single per step; skipped on last iteration) ----
        if (t < T_) {
            __syncthreads();
            if (tid == 0) {
                ++epoch;
                __threadfence();
                unsigned old = atomicAdd(&g_count, 1u);
                if (old == epoch * NCTA - 1u) {
                    g_release = epoch;
                } else {
                    while (g_release < epoch) { }
                }
                __threadfence();
            }
            __syncthreads();
        }
    }

    #undef GEMM_SLICE
    #undef STORE_Z
}

extern "C" void kernel_launch(void* const* d_in, const int* in_sizes, int n_in,
                              void* d_out, int out_size)
{
    const float* x  = (const float*)d_in[0];
    const float* Wi = (const float*)d_in[1];
    const float* bi = (const float*)d_in[2];
    const float* Ws = (const float*)d_in[3];
    const float* bs = (const float*)d_in[4];
    float* out = (float*)d_out;

    cudaFuncSetAttribute(recurrent_kernel,
                         cudaFuncAttributeMaxDynamicSharedMemorySize, SMEM_BYTES);

    init_kernel<<<256, 256>>>();
    precompute_kernel<<<dim3(32, 512), 256>>>(x, Wi, bi, bs);
    recurrent_kernel<<<NCTA, THR, SMEM_BYTES>>>(x, Wi, bi, Ws, bs, out);
}

// round 6
// speedup vs baseline: 1.5114x; 1.2830x over previous
#include <cuda_runtime.h>
#include <cuda_bf16.h>
#include <cstddef>
#include <math.h>

// Problem dims
static constexpr int B_  = 32;
static constexpr int T_  = 1024;
static constexpr int H_  = 512;
static constexpr int G4  = 2048;   // 4*H gate columns per layer
static constexpr int NCTA = 128;   // persistent CTAs, each owns 4 hidden cols
static constexpr int THR  = 512;   // threads per recurrent CTA

// SMEM strides (bank-conflict padding)
static constexpr int AS_STRIDE = 68;   // precompute tiles; 68*4B%16==0
static constexpr int W_STRIDE  = 516;  // 516%32=4 -> 8 jj rows cover all banks; 16B aligned rows
static constexpr int Z_STRIDE  = 36;   // 36%32=4; 16B aligned rows

// Recurrent SMEM layout (floats): weights | h staging | z partials
static constexpr int W_S_FLOATS = 3 * 16 * W_STRIDE;        // 24768
static constexpr int H_S_FLOATS = H_ * B_;                  // 16384
static constexpr int Z_S_FLOATS = 2 * 8 * 16 * Z_STRIDE;    // 9216
static constexpr int SMEM_BYTES = (W_S_FLOATS + H_S_FLOATS + Z_S_FLOATS) * 4; // 201472

// -------- device-global scratch (allocations forbidden) --------
__device__ float    g_Z0p[(size_t)T_ * G4 * B_];   // [t][gate_col][b]
__device__ float    g_h[2][2][H_][B_];             // [layer][parity][col][b]
__device__ unsigned g_count;                       // grid-barrier arrivals (cumulative)
__device__ volatile unsigned g_release;            // grid-barrier release epoch

__device__ __forceinline__ float fsigm(float z) { return 1.0f / (1.0f + __expf(-z)); }
__device__ __forceinline__ float ftanh(float z) { return 2.0f / (1.0f + __expf(-2.0f * z)) - 1.0f; }

__device__ __forceinline__ unsigned long long dup2(float v) {
    unsigned long long r;
    asm("mov.b64 %0, {%1, %1};" : "=l"(r) : "f"(v));
    return r;
}
__device__ __forceinline__ void fma2(unsigned long long& acc,
                                     unsigned long long a, unsigned long long b) {
    asm("fma.rn.f32x2 %0, %1, %2, %0;" : "+l"(acc) : "l"(a), "l"(b));
}

// -------- init: reset barrier + zero states (every launch, graph-safe) --------
__global__ void init_kernel() {
    int idx = blockIdx.x * blockDim.x + threadIdx.x;
    if (idx == 0) { g_count = 0u; g_release = 0u; }
    if (idx < 2 * 2 * H_ * B_) reinterpret_cast<float*>(g_h)[idx] = 0.0f;
}

// -------- precompute: Z0p[t][j][b] = (x @ Wi0^T)[m=b*T+t][j] + bi0[j] + bs0[j] --------
// M=32768, N=2048, K=512. 64x64 tile, 256 threads, 4x4 per thread, packed f32x2.
__global__ void __launch_bounds__(256) precompute_kernel(
    const float* __restrict__ x, const float* __restrict__ Wi,
    const float* __restrict__ bi, const float* __restrict__ bs)
{
    __shared__ float As[16 * AS_STRIDE];   // transposed [k][64]
    __shared__ float Bs[16 * AS_STRIDE];
    const int tid = threadIdx.x;
    const int m0 = blockIdx.y * 64;
    const int j0 = blockIdx.x * 64;
    const int lr = tid >> 2;
    const int lq = tid & 3;
    const int tx = tid & 15;
    const int ty = tid >> 4;

    unsigned long long C2[4][2] = {};
    const float* Arow = x  + (size_t)(m0 + lr) * H_ + lq * 4;
    const float* Brow = Wi + (size_t)(j0 + lr) * H_ + lq * 4;

    for (int kc = 0; kc < H_; kc += 16) {
        float4 a4 = *(const float4*)(Arow + kc);
        float4 b4 = *(const float4*)(Brow + kc);
        __syncthreads();
        As[(lq * 4 + 0) * AS_STRIDE + lr] = a4.x;
        As[(lq * 4 + 1) * AS_STRIDE + lr] = a4.y;
        As[(lq * 4 + 2) * AS_STRIDE + lr] = a4.z;
        As[(lq * 4 + 3) * AS_STRIDE + lr] = a4.w;
        Bs[(lq * 4 + 0) * AS_STRIDE + lr] = b4.x;
        Bs[(lq * 4 + 1) * AS_STRIDE + lr] = b4.y;
        Bs[(lq * 4 + 2) * AS_STRIDE + lr] = b4.z;
        Bs[(lq * 4 + 3) * AS_STRIDE + lr] = b4.w;
        __syncthreads();
        #pragma unroll
        for (int k = 0; k < 16; k++) {
            float4 av = *(const float4*)&As[k * AS_STRIDE + ty * 4];
            ulonglong2 bp = *(const ulonglong2*)&Bs[k * AS_STRIDE + tx * 4];
            #pragma unroll
            for (int i = 0; i < 4; i++) {
                float a = (i == 0) ? av.x : (i == 1) ? av.y : (i == 2) ? av.z : av.w;
                unsigned long long a2 = dup2(a);
                fma2(C2[i][0], bp.x, a2);
                fma2(C2[i][1], bp.y, a2);
            }
        }
    }
    #pragma unroll
    for (int i = 0; i < 4; i++) {
        int m = m0 + ty * 4 + i;
        int bb = m >> 10, tt = m & 1023;
        #pragma unroll
        for (int jp = 0; jp < 2; jp++) {
            float lo, hi;
            asm("mov.b64 {%0, %1}, %2;" : "=f"(lo), "=f"(hi) : "l"(C2[i][jp]));
            int jg = j0 + tx * 4 + jp * 2;
            g_Z0p[((size_t)tt * G4 + jg + 0) * B_ + bb] = lo + bi[jg + 0] + bs[jg + 0];
            g_Z0p[((size_t)tt * G4 + jg + 1) * B_ + bb] = hi + bi[jg + 1] + bs[jg + 1];
        }
    }
}

// -------- cp.async staging helpers --------
__device__ __forceinline__ void stage_async(float* dst, const float* src, int tid) {
    unsigned s = (unsigned)__cvta_generic_to_shared(dst) + tid * 16;
    const char* g = (const char*)src + tid * 16;
    #pragma unroll
    for (int i = 0; i < 8; i++)
        asm volatile("cp.async.cg.shared.global [%0], [%1], 16;"
                     :: "r"(s + i * THR * 16), "l"(g + i * THR * 16) : "memory");
    asm volatile("cp.async.commit_group;" ::: "memory");
}
#define WAIT_CP() asm volatile("cp.async.wait_group 0;" ::: "memory")

// -------- recurrent persistent kernel (layer-pipelined, one grid sync/step) ----
// Iteration t (0..T_): layer0 computes time t (t<T_); layer1 computes time t-1 (t>=1).
__global__ void __launch_bounds__(THR, 1) recurrent_kernel(
    const float* __restrict__ x, const float* __restrict__ Wi,
    const float* __restrict__ bi, const float* __restrict__ Ws,
    const float* __restrict__ bs, float* __restrict__ out)
{
    extern __shared__ float smem[];
    float* w_s = smem;                       // [3][16][W_STRIDE]
    float* h_s = smem + W_S_FLOATS;          // [512][32]
    float* z_s = h_s + H_S_FLOATS;           // [2][8][16][Z_STRIDE]

    const int tid = threadIdx.x;
    const int cta = blockIdx.x;

    // ---- load weight slices into SMEM once ----
    // slice 0: Ws layer0, slice 1: Wi layer1, slice 2: Ws layer1
    for (int idx = tid; idx < 48 * 128; idx += THR) {
        int r = idx >> 7, q = idx & 127;
        int s = r >> 4, jjr = r & 15;
        int g = jjr >> 2, cc = jjr & 3;
        int grow = g * H_ + cta * 4 + cc;
        const float* src;
        if (s == 0)      src = Ws + (size_t)grow * H_;
        else if (s == 1) src = Wi + (size_t)(G4 + grow) * H_;
        else             src = Ws + (size_t)(G4 + grow) * H_;
        *(float4*)(w_s + r * W_STRIDE + q * 4) = *(const float4*)(src + q * 4);
    }

    // ---- GEMM thread constants: bg(4 b-groups of 8) x jj(16 cols) x ks(8 K-splits) ----
    const int bg = tid & 3;
    const int jj = (tid >> 2) & 15;
    const int ks = tid >> 6;

    // ---- cell thread constants (tid < 256): layer, 4 cols, 32 b ----
    const bool is_cell = tid < 256;
    const int layer = (tid >> 7) & 1;
    const int ub  = tid & 31;
    const int ucc = (tid >> 5) & 3;
    const int col = cta * 4 + ucc;

    float b1g0 = 0.f, b1g1 = 0.f, b1g2 = 0.f, b1g3 = 0.f;
    if (is_cell && layer == 1) {
        b1g0 = bi[G4 + 0 * H_ + col] + bs[G4 + 0 * H_ + col];
        b1g1 = bi[G4 + 1 * H_ + col] + bs[G4 + 1 * H_ + col];
        b1g2 = bi[G4 + 2 * H_ + col] + bs[G4 + 2 * H_ + col];
        b1g3 = bi[G4 + 3 * H_ + col] + bs[G4 + 3 * H_ + col];
    }

    float cst = 0.0f;     // this cell thread's c (layer 0 or 1)
    unsigned epoch = 0;

    const ulonglong2* h2 = (const ulonglong2*)h_s;

    const float* w0r = w_s + (0 * 16 + jj) * W_STRIDE + ks * 64;
    const float* w1r = w_s + (1 * 16 + jj) * W_STRIDE + ks * 64;
    const float* w2r = w_s + (2 * 16 + jj) * W_STRIDE + ks * 64;

    for (int t = 0; t <= T_; t++) {
        const int cur = t & 1, prv = cur ^ 1;

        // ---- stage h0(t-1) via cp.async; overlap with Z0p/x prefetch ----
        stage_async(h_s, &g_h[0][prv][0][0], tid);
        float zp0 = 0.f, zp1 = 0.f, zp2 = 0.f, zp3 = 0.f, xv = 0.f;
        if (is_cell && layer == 0 && t < T_) {
            zp0 = g_Z0p[((size_t)t * G4 + 0 * H_ + col) * B_ + ub];
            zp1 = g_Z0p[((size_t)t * G4 + 1 * H_ + col) * B_ + ub];
            zp2 = g_Z0p[((size_t)t * G4 + 2 * H_ + col) * B_ + ub];
            zp3 = g_Z0p[((size_t)t * G4 + 3 * H_ + col) * B_ + ub];
            xv  = x[((size_t)ub * T_ + t) * H_ + col];
        }
        WAIT_CP();
        __syncthreads();                       // (a) h_s = h0(t-1)

        // ---- fused slices 0+1: shared h loads, two accumulator sets ----
        unsigned long long S01 = 0, S23 = 0, S45 = 0, S67 = 0;   // layer0 recurrent
        unsigned long long I01 = 0, I23 = 0, I45 = 0, I67 = 0;   // layer1 input
        #pragma unroll 4
        for (int k0 = 0; k0 < 64; k0 += 4) {
            float4 w0 = *(const float4*)(w0r + k0);
            float4 w1 = *(const float4*)(w1r + k0);
            #pragma unroll
            for (int i = 0; i < 4; i++) {
                float wa = (i == 0) ? w0.x : (i == 1) ? w0.y : (i == 2) ? w0.z : w0.w;
                float wb = (i == 0) ? w1.x : (i == 1) ? w1.y : (i == 2) ? w1.z : w1.w;
                unsigned long long wa2 = dup2(wa);
                unsigned long long wb2 = dup2(wb);
                int kk = ks * 64 + k0 + i;
                ulonglong2 hA = h2[kk * 8 + bg * 2 + 0];
                ulonglong2 hB = h2[kk * 8 + bg * 2 + 1];
                fma2(S01, hA.x, wa2); fma2(S23, hA.y, wa2);
                fma2(S45, hB.x, wa2); fma2(S67, hB.y, wa2);
                fma2(I01, hA.x, wb2); fma2(I23, hA.y, wb2);
                fma2(I45, hB.x, wb2); fma2(I67, hB.y, wb2);
            }
        }
        // store layer0 partials
        {
            ulonglong2* zp = (ulonglong2*)(z_s + ((0 * 8 + ks) * 16 + jj) * Z_STRIDE + bg * 8);
            zp[0] = make_ulonglong2(S01, S23);
            zp[1] = make_ulonglong2(S45, S67);
        }
        float h0res = 0.f;
        if (is_cell && layer == 1) h0res = h_s[col * 32 + ub];   // h0(t-1), layer1 residual

        __syncthreads();                       // (b) all h_s reads + z[0] stores done

        // ---- stage h1(t-2); hide latency behind layer-0 cell update ----
        stage_async(h_s, &g_h[1][cur][0][0], tid);

        if (is_cell && layer == 0 && t < T_) {
            float zi = zp0, zf = zp1, zg = zp2, zo = zp3;
            #pragma unroll
            for (int p = 0; p < 8; p++) {
                const float* zr = z_s + (0 * 8 + p) * 16 * Z_STRIDE;
                zi += zr[(0 * 4 + ucc) * Z_STRIDE + ub];
                zf += zr[(1 * 4 + ucc) * Z_STRIDE + ub];
                zg += zr[(2 * 4 + ucc) * Z_STRIDE + ub];
                zo += zr[(3 * 4 + ucc) * Z_STRIDE + ub];
            }
            cst = fmaf(fsigm(zf), cst, fsigm(zi) * ftanh(zg));
            float hv = fmaf(fsigm(zo), ftanh(cst), xv);
            g_h[0][cur][col][ub] = hv;
            if (t == T_ - 1) {
                float* hf = out + (size_t)B_ * T_ * H_;
                float* cf = hf + (size_t)B_ * 2 * H_;
                hf[((size_t)ub * 2 + 0) * H_ + col] = hv;
                cf[((size_t)ub * 2 + 0) * H_ + col] = cst;
            }
        }

        WAIT_CP();
        __syncthreads();                       // (c) h_s = h1(t-2)

        // ---- slice 2: layer1 recurrent GEMM (accumulates into I) ----
        #pragma unroll 4
        for (int k0 = 0; k0 < 64; k0 += 4) {
            float4 w2v = *(const float4*)(w2r + k0);
            #pragma unroll
            for (int i = 0; i < 4; i++) {
                float wc = (i == 0) ? w2v.x : (i == 1) ? w2v.y : (i == 2) ? w2v.z : w2v.w;
                unsigned long long wc2 = dup2(wc);
                int kk = ks * 64 + k0 + i;
                ulonglong2 hA = h2[kk * 8 + bg * 2 + 0];
                ulonglong2 hB = h2[kk * 8 + bg * 2 + 1];
                fma2(I01, hA.x, wc2); fma2(I23, hA.y, wc2);
                fma2(I45, hB.x, wc2); fma2(I67, hB.y, wc2);
            }
        }
        {
            ulonglong2* zp = (ulonglong2*)(z_s + ((1 * 8 + ks) * 16 + jj) * Z_STRIDE + bg * 8);
            zp[0] = make_ulonglong2(I01, I23);
            zp[1] = make_ulonglong2(I45, I67);
        }
        __syncthreads();                       // (d) z[1] ready

        // ---- layer-1 cell update ----
        if (is_cell && layer == 1 && t >= 1) {
            float zi = b1g0, zf = b1g1, zg = b1g2, zo = b1g3;
            #pragma unroll
            for (int p = 0; p < 8; p++) {
                const float* zr = z_s + (1 * 8 + p) * 16 * Z_STRIDE;
                zi += zr[(0 * 4 + ucc) * Z_STRIDE + ub];
                zf += zr[(1 * 4 + ucc) * Z_STRIDE + ub];
                zg += zr[(2 * 4 + ucc) * Z_STRIDE + ub];
                zo += zr[(3 * 4 + ucc) * Z_STRIDE + ub];
            }
            cst = fmaf(fsigm(zf), cst, fsigm(zi) * ftanh(zg));
            float hv = fmaf(fsigm(zo), ftanh(cst), h0res);
            g_h[1][prv][col][ub] = hv;                          // h1(t-1)
            out[((size_t)ub * T_ + (t - 1)) * H_ + col] = hv;
            if (t == T_) {
                float* hf = out + (size_t)B_ * T_ * H_;
                float* cf = hf + (size_t)B_ * 2 * H_;
                hf[((size_t)ub * 2 + 1) * H_ + col] = hv;
                cf[((size_t)ub * 2 + 1) * H_ + col] = cst;
            }
        }

        // ---- grid barrier (single per step; skipped on last iteration) ----
        if (t < T_) {
            __syncthreads();
            if (tid == 0) {
                ++epoch;
                __threadfence();
                unsigned old = atomicAdd(&g_count, 1u);
                if (old == epoch * NCTA - 1u) {
                    g_release = epoch;
                } else {
                    while (g_release < epoch) { }
                }
                __threadfence();
            }
            __syncthreads();
        }
    }
}

extern "C" void kernel_launch(void* const* d_in, const int* in_sizes, int n_in,
                              void* d_out, int out_size)
{
    const float* x  = (const float*)d_in[0];
    const float* Wi = (const float*)d_in[1];
    const float* bi = (const float*)d_in[2];
    const float* Ws = (const float*)d_in[3];
    const float* bs = (const float*)d_in[4];
    float* out = (float*)d_out;

    cudaFuncSetAttribute(recurrent_kernel,
                         cudaFuncAttributeMaxDynamicSharedMemorySize, SMEM_BYTES);

    init_kernel<<<256, 256>>>();
    precompute_kernel<<<dim3(32, 512), 256>>>(x, Wi, bi, bs);
    recurrent_kernel<<<NCTA, THR, SMEM_BYTES>>>(x, Wi, bi, Ws, bs, out);
}